// round 10
// baseline (speedup 1.0000x reference)
#include <cuda_runtime.h>
#include <cuda_bf16.h>
#include <math.h>

// ---------------- static scratch (no allocations allowed) ----------------
// sizes: B=64 T=16 H=W=64 C=16 -> BT=1024
__device__ float g_w1t[256 * 64];          // conv1 weights, k-major  (k = dy*64+dx*16+ci)
__device__ float g_w2t[1024 * 256];        // conv2 weights, k-major  (k = dy*256+dx*64+ci)
__device__ float g_h1[1024 * 256 * 64];    // conv1 out, (bt,oh,ow,64) channels-last, post LN+gelu
__device__ float g_c2[16384 * 256];        // conv2 out rows (bt*16+pix, 256); LN+gelu applied in place
__device__ float g_emb[1024 * 512];        // fc out (bt, 512)
__device__ float g_gates[64 * 6];          // gate weights per batch

__device__ __forceinline__ float gelu_f(float v) {
    return 0.5f * v * (1.0f + erff(v * 0.70710678118654752440f));
}

// ---------------- weight re-layout (k-major for GEMM B tiles) ----------------
__global__ void prep_weights(const float* __restrict__ w1, const float* __restrict__ w2) {
    int i = blockIdx.x * 256 + threadIdx.x;
    if (i < 16384) {                 // w1: (co,ci,dy,dx) -> w1t[k*64+co], k=(dy,dx,ci)
        int k = i >> 6, co = i & 63;
        int dy = k >> 6, dx = (k >> 4) & 3, ci = k & 15;
        g_w1t[i] = w1[((co * 16 + ci) * 4 + dy) * 4 + dx];
    }
    if (i < 262144) {                // w2: (co,ci,dy,dx) -> w2t[k*256+co], k=(dy,dx,ci)
        int k = i >> 8, co = i & 255;
        int dy = k >> 8, dx = (k >> 6) & 3, ci = k & 63;
        g_w2t[i] = w2[((co * 64 + ci) * 4 + dy) * 4 + dx];
    }
}

// =======================================================================
// conv1 as implicit GEMM: M=262144 (bt*256+oh*16+ow), N=64, K=256
// block: 64 m-rows x 64 n-cols, 256 threads, 4x4 per thread, K-chunks of 64 (=dy)
// epilogue: bias + LayerNorm(64) + gelu fused (block owns full channel dim)
// =======================================================================
__global__ __launch_bounds__(256) void conv1_kernel(
    const float* __restrict__ x, const float* __restrict__ bias,
    const float* __restrict__ lng, const float* __restrict__ lnb)
{
    __shared__ float As[64 * 68];
    __shared__ float Bs[64 * 68];
    const int tid = threadIdx.x;
    const int tn = tid & 15;        // n group: cols tn*4 .. tn*4+3
    const int tm = tid >> 4;        // m rows: tm, tm+16, tm+32, tm+48
    const int ml = tid >> 2;        // load row
    const int q  = tid & 3;         // load quad
    const int m0 = blockIdx.x * 64;
    const int mg = m0 + ml;
    const int bt = mg >> 8;
    const int oh = (mg >> 4) & 15;
    const int ow = mg & 15;
    const float4* x4 = reinterpret_cast<const float4*>(x);
    const float4* w4 = reinterpret_cast<const float4*>(g_w1t);

    float acc[4][4];
#pragma unroll
    for (int i = 0; i < 4; i++)
#pragma unroll
        for (int j = 0; j < 4; j++) acc[i][j] = 0.f;

    float4 ra[4], rb[4];
    {   // prologue chunk 0
        int abase = ((bt * 64 + oh * 4 + 0) * 64 + ow * 4) * 4;
        int bbase = (0 * 64 + ml) * 16;
#pragma unroll
        for (int it = 0; it < 4; it++) { ra[it] = x4[abase + q + 4 * it]; rb[it] = w4[bbase + q + 4 * it]; }
    }
    for (int c = 0; c < 4; c++) {
        __syncthreads();
#pragma unroll
        for (int it = 0; it < 4; it++) {
            *reinterpret_cast<float4*>(&As[ml * 68 + (q + 4 * it) * 4]) = ra[it];
            *reinterpret_cast<float4*>(&Bs[ml * 68 + (q + 4 * it) * 4]) = rb[it];
        }
        __syncthreads();
        if (c + 1 < 4) {
            int abase = ((bt * 64 + oh * 4 + (c + 1)) * 64 + ow * 4) * 4;
            int bbase = ((c + 1) * 64 + ml) * 16;
#pragma unroll
            for (int it = 0; it < 4; it++) { ra[it] = x4[abase + q + 4 * it]; rb[it] = w4[bbase + q + 4 * it]; }
        }
#pragma unroll 16
        for (int kk = 0; kk < 64; kk++) {
            float4 b4 = *reinterpret_cast<const float4*>(&Bs[kk * 68 + tn * 4]);
            float a0 = As[(tm     ) * 68 + kk];
            float a1 = As[(tm + 16) * 68 + kk];
            float a2 = As[(tm + 32) * 68 + kk];
            float a3 = As[(tm + 48) * 68 + kk];
            acc[0][0] += a0 * b4.x; acc[0][1] += a0 * b4.y; acc[0][2] += a0 * b4.z; acc[0][3] += a0 * b4.w;
            acc[1][0] += a1 * b4.x; acc[1][1] += a1 * b4.y; acc[1][2] += a1 * b4.z; acc[1][3] += a1 * b4.w;
            acc[2][0] += a2 * b4.x; acc[2][1] += a2 * b4.y; acc[2][2] += a2 * b4.z; acc[2][3] += a2 * b4.w;
            acc[3][0] += a3 * b4.x; acc[3][1] += a3 * b4.y; acc[3][2] += a3 * b4.z; acc[3][3] += a3 * b4.w;
        }
    }
    // ---- epilogue: bias, LN(64), gelu ----
    __syncthreads();
#pragma unroll
    for (int mi = 0; mi < 4; mi++) {
        int r = tm + 16 * mi;
#pragma unroll
        for (int ni = 0; ni < 4; ni++)
            As[r * 68 + tn * 4 + ni] = acc[mi][ni] + bias[tn * 4 + ni];
    }
    __syncthreads();
    if (tid < 64) {
        float s = 0.f, ss = 0.f;
#pragma unroll 8
        for (int j = 0; j < 64; j++) { float v = As[tid * 68 + j]; s += v; ss += v * v; }
        float mean = s * (1.f / 64.f);
        float var  = ss * (1.f / 64.f) - mean * mean;
        Bs[tid] = mean;
        Bs[64 + tid] = rsqrtf(var + 1e-5f);
    }
    __syncthreads();
#pragma unroll
    for (int mi = 0; mi < 4; mi++) {
        int r = tm + 16 * mi;
        float mean = Bs[r], rstd = Bs[64 + r];
        float4 o;
        float v;
        v = (As[r * 68 + tn * 4 + 0] - mean) * rstd * lng[tn * 4 + 0] + lnb[tn * 4 + 0]; o.x = gelu_f(v);
        v = (As[r * 68 + tn * 4 + 1] - mean) * rstd * lng[tn * 4 + 1] + lnb[tn * 4 + 1]; o.y = gelu_f(v);
        v = (As[r * 68 + tn * 4 + 2] - mean) * rstd * lng[tn * 4 + 2] + lnb[tn * 4 + 2]; o.z = gelu_f(v);
        v = (As[r * 68 + tn * 4 + 3] - mean) * rstd * lng[tn * 4 + 3] + lnb[tn * 4 + 3]; o.w = gelu_f(v);
        *reinterpret_cast<float4*>(&g_h1[(m0 + r) * 64 + tn * 4]) = o;
    }
}

// =======================================================================
// conv2 as implicit GEMM: M=16384 (bt*16+oh*4+ow), N=256, K=1024
// grid (256 m-tiles, 4 n-tiles). Writes pre-LN to g_c2.
// =======================================================================
__global__ __launch_bounds__(256) void conv2_kernel(const float* __restrict__ bias)
{
    __shared__ float As[64 * 68];
    __shared__ float Bs[64 * 68];
    const int tid = threadIdx.x;
    const int tn = tid & 15;
    const int tm = tid >> 4;
    const int ml = tid >> 2;
    const int q  = tid & 3;
    const int m0 = blockIdx.x * 64;
    const int n0 = blockIdx.y * 64;
    const int mg = m0 + ml;
    const int bt = mg >> 4;
    const int oh = (mg >> 2) & 3;
    const int ow = mg & 3;
    const float4* h4 = reinterpret_cast<const float4*>(g_h1);
    const float4* w4 = reinterpret_cast<const float4*>(g_w2t);

    float acc[4][4];
#pragma unroll
    for (int i = 0; i < 4; i++)
#pragma unroll
        for (int j = 0; j < 4; j++) acc[i][j] = 0.f;

    float4 ra[4], rb[4];
    {
        int dy = 0, dx = 0;
        int abase = (bt * 256 + (oh * 4 + dy) * 16 + ow * 4 + dx) * 16;
        int bbase = (0 * 64 + ml) * 64 + (n0 >> 2);
#pragma unroll
        for (int it = 0; it < 4; it++) { ra[it] = h4[abase + q + 4 * it]; rb[it] = w4[bbase + q + 4 * it]; }
    }
    for (int c = 0; c < 16; c++) {
        __syncthreads();
#pragma unroll
        for (int it = 0; it < 4; it++) {
            *reinterpret_cast<float4*>(&As[ml * 68 + (q + 4 * it) * 4]) = ra[it];
            *reinterpret_cast<float4*>(&Bs[ml * 68 + (q + 4 * it) * 4]) = rb[it];
        }
        __syncthreads();
        if (c + 1 < 16) {
            int cn = c + 1;
            int dy = cn >> 2, dx = cn & 3;
            int abase = (bt * 256 + (oh * 4 + dy) * 16 + ow * 4 + dx) * 16;
            int bbase = (cn * 64 + ml) * 64 + (n0 >> 2);
#pragma unroll
            for (int it = 0; it < 4; it++) { ra[it] = h4[abase + q + 4 * it]; rb[it] = w4[bbase + q + 4 * it]; }
        }
#pragma unroll 16
        for (int kk = 0; kk < 64; kk++) {
            float4 b4 = *reinterpret_cast<const float4*>(&Bs[kk * 68 + tn * 4]);
            float a0 = As[(tm     ) * 68 + kk];
            float a1 = As[(tm + 16) * 68 + kk];
            float a2 = As[(tm + 32) * 68 + kk];
            float a3 = As[(tm + 48) * 68 + kk];
            acc[0][0] += a0 * b4.x; acc[0][1] += a0 * b4.y; acc[0][2] += a0 * b4.z; acc[0][3] += a0 * b4.w;
            acc[1][0] += a1 * b4.x; acc[1][1] += a1 * b4.y; acc[1][2] += a1 * b4.z; acc[1][3] += a1 * b4.w;
            acc[2][0] += a2 * b4.x; acc[2][1] += a2 * b4.y; acc[2][2] += a2 * b4.z; acc[2][3] += a2 * b4.w;
            acc[3][0] += a3 * b4.x; acc[3][1] += a3 * b4.y; acc[3][2] += a3 * b4.z; acc[3][3] += a3 * b4.w;
        }
    }
#pragma unroll
    for (int mi = 0; mi < 4; mi++) {
        int r = tm + 16 * mi;
        float4 o;
        o.x = acc[mi][0] + bias[n0 + tn * 4 + 0];
        o.y = acc[mi][1] + bias[n0 + tn * 4 + 1];
        o.z = acc[mi][2] + bias[n0 + tn * 4 + 2];
        o.w = acc[mi][3] + bias[n0 + tn * 4 + 3];
        *reinterpret_cast<float4*>(&g_c2[(m0 + r) * 256 + n0 + tn * 4]) = o;
    }
}

// ---------------- LN(256) + gelu, in place on g_c2 ----------------
__global__ __launch_bounds__(256) void ln2_kernel(const float* __restrict__ lng, const float* __restrict__ lnb)
{
    int row = blockIdx.x, tid = threadIdx.x;
    float v = g_c2[row * 256 + tid];
    float a = v, qq = v * v;
#pragma unroll
    for (int o = 16; o > 0; o >>= 1) {
        a  += __shfl_down_sync(0xffffffffu, a,  o);
        qq += __shfl_down_sync(0xffffffffu, qq, o);
    }
    __shared__ float s1[8], s2[8];
    __shared__ float sm, sr;
    if ((tid & 31) == 0) { s1[tid >> 5] = a; s2[tid >> 5] = qq; }
    __syncthreads();
    if (tid == 0) {
        float A = 0.f, Q = 0.f;
#pragma unroll
        for (int i = 0; i < 8; i++) { A += s1[i]; Q += s2[i]; }
        float mean = A * (1.f / 256.f);
        float var  = Q * (1.f / 256.f) - mean * mean;
        sm = mean; sr = rsqrtf(var + 1e-5f);
    }
    __syncthreads();
    float xo = (v - sm) * sr * lng[tid] + lnb[tid];
    g_c2[row * 256 + tid] = gelu_f(xo);
}

// =======================================================================
// FC: M=1024, N=512, K=4096 ; A=g_c2 (rows of 4096), B=fc_w (k-major)
// =======================================================================
__global__ __launch_bounds__(256) void fc_kernel(const float* __restrict__ fcw, const float* __restrict__ fcb)
{
    __shared__ float As[64 * 68];
    __shared__ float Bs[64 * 68];
    const int tid = threadIdx.x;
    const int tn = tid & 15;
    const int tm = tid >> 4;
    const int ml = tid >> 2;
    const int q  = tid & 3;
    const int m0 = blockIdx.x * 64;
    const int n0 = blockIdx.y * 64;
    const float4* a4 = reinterpret_cast<const float4*>(g_c2);
    const float4* b4p = reinterpret_cast<const float4*>(fcw);

    float acc[4][4];
#pragma unroll
    for (int i = 0; i < 4; i++)
#pragma unroll
        for (int j = 0; j < 4; j++) acc[i][j] = 0.f;

    float4 ra[4], rb[4];
    {
        int abase = (m0 + ml) * 1024 + 0 * 16;
        int bbase = (0 * 64 + ml) * 128 + (n0 >> 2);
#pragma unroll
        for (int it = 0; it < 4; it++) { ra[it] = a4[abase + q + 4 * it]; rb[it] = b4p[bbase + q + 4 * it]; }
    }
    for (int c = 0; c < 64; c++) {
        __syncthreads();
#pragma unroll
        for (int it = 0; it < 4; it++) {
            *reinterpret_cast<float4*>(&As[ml * 68 + (q + 4 * it) * 4]) = ra[it];
            *reinterpret_cast<float4*>(&Bs[ml * 68 + (q + 4 * it) * 4]) = rb[it];
        }
        __syncthreads();
        if (c + 1 < 64) {
            int abase = (m0 + ml) * 1024 + (c + 1) * 16;
            int bbase = ((c + 1) * 64 + ml) * 128 + (n0 >> 2);
#pragma unroll
            for (int it = 0; it < 4; it++) { ra[it] = a4[abase + q + 4 * it]; rb[it] = b4p[bbase + q + 4 * it]; }
        }
#pragma unroll 16
        for (int kk = 0; kk < 64; kk++) {
            float4 b4 = *reinterpret_cast<const float4*>(&Bs[kk * 68 + tn * 4]);
            float a0 = As[(tm     ) * 68 + kk];
            float a1 = As[(tm + 16) * 68 + kk];
            float a2 = As[(tm + 32) * 68 + kk];
            float a3 = As[(tm + 48) * 68 + kk];
            acc[0][0] += a0 * b4.x; acc[0][1] += a0 * b4.y; acc[0][2] += a0 * b4.z; acc[0][3] += a0 * b4.w;
            acc[1][0] += a1 * b4.x; acc[1][1] += a1 * b4.y; acc[1][2] += a1 * b4.z; acc[1][3] += a1 * b4.w;
            acc[2][0] += a2 * b4.x; acc[2][1] += a2 * b4.y; acc[2][2] += a2 * b4.z; acc[2][3] += a2 * b4.w;
            acc[3][0] += a3 * b4.x; acc[3][1] += a3 * b4.y; acc[3][2] += a3 * b4.z; acc[3][3] += a3 * b4.w;
        }
    }
#pragma unroll
    for (int mi = 0; mi < 4; mi++) {
        int r = tm + 16 * mi;
        float4 o;
        o.x = acc[mi][0] + fcb[n0 + tn * 4 + 0];
        o.y = acc[mi][1] + fcb[n0 + tn * 4 + 1];
        o.z = acc[mi][2] + fcb[n0 + tn * 4 + 2];
        o.w = acc[mi][3] + fcb[n0 + tn * 4 + 3];
        *reinterpret_cast<float4*>(&g_emb[(m0 + r) * 512 + n0 + tn * 4]) = o;
    }
}

// =======================================================================
// Fourier top-2 gating. One block per batch, 512 threads (one per d).
// rfft over T=16 (bins 1..8, ortho), amp, mean over d, @ w_gate, top-2 softmax.
// =======================================================================
__global__ __launch_bounds__(512) void gate_kernel(const float* __restrict__ wg)
{
    int b = blockIdx.x, tid = threadIdx.x;
    float v[16];
#pragma unroll
    for (int t = 0; t < 16; t++) v[t] = g_emb[(b * 16 + t) * 512 + tid];
    float amp[8];
#pragma unroll
    for (int f = 1; f <= 8; f++) {
        float re = 0.f, im = 0.f;
#pragma unroll
        for (int t = 0; t < 16; t++) {
            float ang = (float)(f * t) * 0.125f;   // angle/pi
            re += v[t] * cospif(ang);
            im -= v[t] * sinpif(ang);
        }
        amp[f - 1] = 0.25f * sqrtf(re * re + im * im);
    }
    __shared__ float red[512];
    __shared__ float asum[8];
    for (int j = 0; j < 8; j++) {
        red[tid] = amp[j];
        __syncthreads();
        for (int s = 256; s > 0; s >>= 1) {
            if (tid < s) red[tid] += red[tid + s];
            __syncthreads();
        }
        if (tid == 0) asum[j] = red[0];
        __syncthreads();
    }
    if (tid == 0) {
        float w[6];
        for (int e = 0; e < 6; e++) {
            float acc = 0.f;
            for (int f = 0; f < 8; f++) acc += asum[f] * (1.f / 512.f) * wg[f * 6 + e];
            w[e] = acc;
        }
        int i1 = 0;
        for (int e = 1; e < 6; e++) if (w[e] > w[i1]) i1 = e;
        int i2 = (i1 == 0) ? 1 : 0;
        for (int e = 0; e < 6; e++) if (e != i1 && w[e] > w[i2]) i2 = e;
        float e2 = expf(w[i2] - w[i1]);
        float s = 1.f + e2;
        for (int e = 0; e < 6; e++) g_gates[b * 6 + e] = 0.f;
        g_gates[b * 6 + i1] = 1.f / s;
        g_gates[b * 6 + i2] = e2 / s;
    }
}

// =======================================================================
// Experts: per (b, 128-col tile) block. Loops the (<=2) gated experts:
// GEMM 16x128 @ K=512, then comb += g * exp(val+bias); out = log(comb).
// =======================================================================
__global__ __launch_bounds__(256) void expert_kernel(
    const float* __restrict__ ew, const float* __restrict__ eb, float* __restrict__ out)
{
    __shared__ float As[16 * 68];
    __shared__ float Bs[64 * 132];
    const int b  = blockIdx.x;
    const int n0 = blockIdx.y * 128;
    const int tid = threadIdx.x;
    const int tn  = tid & 63;     // col pair: n0 + tn*2, +1
    const int tmg = tid >> 6;     // rows tmg*4 .. tmg*4+3
    const int arow = tid >> 4, ap = tid & 15;   // A load map (16 rows x 16 float4)
    const int brow = tid >> 2, bq = tid & 3;    // B load map (64 rows x 32 float4)
    const float4* e4 = reinterpret_cast<const float4*>(g_emb);
    const float4* w4 = reinterpret_cast<const float4*>(ew);

    float comb[4][2] = {{0.f,0.f},{0.f,0.f},{0.f,0.f},{0.f,0.f}};

    for (int e = 0; e < 6; e++) {
        float g = g_gates[b * 6 + e];
        if (g == 0.f) continue;   // uniform per block
        float acc[4][2] = {{0.f,0.f},{0.f,0.f},{0.f,0.f},{0.f,0.f}};
        float4 ra; float4 rb[8];
        {
            ra = e4[(b * 16 + arow) * 128 + 0 * 16 + ap];
            int bb = (e * 512 + 0 * 64 + brow) * 128 + (n0 >> 2);
#pragma unroll
            for (int it = 0; it < 8; it++) rb[it] = w4[bb + bq + 4 * it];
        }
        for (int c = 0; c < 8; c++) {
            __syncthreads();
            *reinterpret_cast<float4*>(&As[arow * 68 + ap * 4]) = ra;
#pragma unroll
            for (int it = 0; it < 8; it++)
                *reinterpret_cast<float4*>(&Bs[brow * 132 + (bq + 4 * it) * 4]) = rb[it];
            __syncthreads();
            if (c + 1 < 8) {
                ra = e4[(b * 16 + arow) * 128 + (c + 1) * 16 + ap];
                int bb = (e * 512 + (c + 1) * 64 + brow) * 128 + (n0 >> 2);
#pragma unroll
                for (int it = 0; it < 8; it++) rb[it] = w4[bb + bq + 4 * it];
            }
#pragma unroll 16
            for (int kk = 0; kk < 64; kk++) {
                float2 bv = *reinterpret_cast<const float2*>(&Bs[kk * 132 + tn * 2]);
                float a0 = As[(tmg * 4 + 0) * 68 + kk];
                float a1 = As[(tmg * 4 + 1) * 68 + kk];
                float a2 = As[(tmg * 4 + 2) * 68 + kk];
                float a3 = As[(tmg * 4 + 3) * 68 + kk];
                acc[0][0] += a0 * bv.x; acc[0][1] += a0 * bv.y;
                acc[1][0] += a1 * bv.x; acc[1][1] += a1 * bv.y;
                acc[2][0] += a2 * bv.x; acc[2][1] += a2 * bv.y;
                acc[3][0] += a3 * bv.x; acc[3][1] += a3 * bv.y;
            }
        }
        float bb0 = eb[e * 512 + n0 + tn * 2 + 0];
        float bb1 = eb[e * 512 + n0 + tn * 2 + 1];
#pragma unroll
        for (int i = 0; i < 4; i++) {
            comb[i][0] += g * expf(acc[i][0] + bb0);
            comb[i][1] += g * expf(acc[i][1] + bb1);
        }
    }
#pragma unroll
    for (int i = 0; i < 4; i++) {
        int m = tmg * 4 + i;
        float c0 = comb[i][0]; if (c0 == 0.f) c0 = 2.2204460492503131e-16f;
        float c1 = comb[i][1]; if (c1 == 0.f) c1 = 2.2204460492503131e-16f;
        float2 o = make_float2(logf(c0), logf(c1));
        *reinterpret_cast<float2*>(&out[(b * 16 + m) * 512 + n0 + tn * 2]) = o;
    }
}

// ---------------- launcher ----------------
extern "C" void kernel_launch(void* const* d_in, const int* in_sizes, int n_in,
                              void* d_out, int out_size)
{
    (void)in_sizes; (void)n_in; (void)out_size;
    const float* x   = (const float*)d_in[0];
    const float* w1  = (const float*)d_in[1];
    const float* b1  = (const float*)d_in[2];
    const float* g1  = (const float*)d_in[3];
    const float* be1 = (const float*)d_in[4];
    const float* w2  = (const float*)d_in[5];
    const float* b2  = (const float*)d_in[6];
    const float* g2  = (const float*)d_in[7];
    const float* be2 = (const float*)d_in[8];
    const float* fcw = (const float*)d_in[9];
    const float* fcb = (const float*)d_in[10];
    const float* wg  = (const float*)d_in[11];
    const float* ew  = (const float*)d_in[12];
    const float* eb  = (const float*)d_in[13];
    float* out = (float*)d_out;

    prep_weights<<<1024, 256>>>(w1, w2);
    conv1_kernel<<<4096, 256>>>(x, b1, g1, be1);
    conv2_kernel<<<dim3(256, 4), 256>>>(b2);
    ln2_kernel<<<16384, 256>>>(g2, be2);
    fc_kernel<<<dim3(16, 8), 256>>>(fcw, fcb);
    gate_kernel<<<64, 512>>>(wg);
    expert_kernel<<<dim3(64, 4), 256>>>(ew, eb, out);
}